// round 2
// baseline (speedup 1.0000x reference)
#include <cuda_runtime.h>
#include <cstdint>

// PosRegressor_43482248904949 — batched bilinear shift with mirror boundary.
// images: (256, 512, 512, 1) fp32, dxdy: (256, 2) fp32 -> out: (256, 512, 512) fp32.
//
// Memory-bound: 512 MB total traffic, roofline floor ~65-75 us on GB300.
// One block per (batch, row). Per-image dy/dx are scalars, so row pointers
// (y0m, y1m) and fy are computed once per block; per-thread work is the
// x-direction floor/frac + mirror + 4 gathers + 3 FMAs.

#define H 512
#define W 512

__device__ __forceinline__ int mirror_idx(int idx, int n) {
    // p = 2*(n-1); i = |idx| mod p; if i >= n: i = p - i
    const int p = 2 * (n - 1);
    int i = idx < 0 ? -idx : idx;
    i = i % p;                  // idx range is small; % is fine (not in hot path per-byte)
    return (i >= n) ? (p - i) : i;
}

__global__ void __launch_bounds__(256, 8)
shift_bilinear_kernel(const float* __restrict__ img,
                      const float* __restrict__ dxdy,
                      float* __restrict__ out) {
    const int y = blockIdx.x;   // output row
    const int b = blockIdx.y;   // batch image

    // Per-image shift (dy = dxdy[b,0], dx = dxdy[b,1])
    const float dy = __ldg(&dxdy[2 * b + 0]);
    const float dx = __ldg(&dxdy[2 * b + 1]);

    // Replicate the reference's exact fp32 sequence for the y direction.
    const float cy  = (float)y - dy;
    const float y0f = floorf(cy);
    const float fy  = cy - y0f;
    const int   y0  = (int)y0f;
    const int   y0m = mirror_idx(y0,     H);
    const int   y1m = mirror_idx(y0 + 1, H);

    const size_t base = (size_t)b * H * W;
    const float* __restrict__ row0 = img + base + (size_t)y0m * W;
    const float* __restrict__ row1 = img + base + (size_t)y1m * W;
    float* __restrict__ orow = out + base + (size_t)y * W;

    #pragma unroll
    for (int x = threadIdx.x; x < W; x += 256) {
        const float cx  = (float)x - dx;
        const float x0f = floorf(cx);
        const float fx  = cx - x0f;
        const int   x0  = (int)x0f;
        const int   x0m = mirror_idx(x0,     W);
        const int   x1m = mirror_idx(x0 + 1, W);

        const float v00 = __ldg(row0 + x0m);
        const float v01 = __ldg(row0 + x1m);
        const float v10 = __ldg(row1 + x0m);
        const float v11 = __ldg(row1 + x1m);

        // (1-fx)*v00 + fx*v01 == v00 + fx*(v01-v00); continuous in weights,
        // so any 1-ulp floor-boundary disagreement vs reference stays tiny.
        const float top = fmaf(fx, v01 - v00, v00);
        const float bot = fmaf(fx, v11 - v10, v10);
        orow[x] = fmaf(fy, bot - top, top);
    }
}

extern "C" void kernel_launch(void* const* d_in, const int* in_sizes, int n_in,
                              void* d_out, int out_size) {
    const float* images = (const float*)d_in[0];  // (256,512,512,1)
    const float* dxdy   = (const float*)d_in[1];  // (256,2)
    float* out = (float*)d_out;                   // (256,512,512)

    const int B = in_sizes[1] / 2;                // 256
    dim3 grid(H, B);
    shift_bilinear_kernel<<<grid, 256>>>(images, dxdy, out);
}